// round 2
// baseline (speedup 1.0000x reference)
#include <cuda_runtime.h>
#include <math.h>

// Problem constants
#define BQ 4      // batch
#define LQ 2048   // sequence length
#define EQ 256    // head dim (= embed dim)
#define HQ 8      // heads
#define GRP 8     // bh-slices per scores-buffer chunk (32 total -> 4 groups)

// ---------------------------------------------------------------------------
// Scratch (device globals: allocation-free). 384 MB total.
// ---------------------------------------------------------------------------
__device__ float g_q [BQ*HQ*LQ*EQ];           // [bh][l][e], pre-scaled by 1/sqrt(E)   (64 MB)
__device__ float g_kt[BQ*HQ*EQ*LQ];           // [bh][e][l]  (transposed K)            (64 MB)
__device__ float g_v [BQ*HQ*LQ*EQ];           // [bh][l][e]                            (64 MB)
__device__ float g_s [(size_t)GRP*LQ*LQ];     // [bh_local][l][l] scores chunk         (128 MB)
__device__ float g_att[(size_t)BQ*LQ*HQ*EQ];  // [b][l][h*E+e]                         (64 MB)

// ---------------------------------------------------------------------------
// Generic 128x128x8 SGEMM, 256 threads, 8x8 microtile, vectorized ld/st.
// All problem dims are exact multiples of tile sizes -> no bounds checks.
// MODE 0: qkv = x @ W_qkv          (epilogue scatters to g_q/g_kt/g_v)
// MODE 1: s   = q_bh @ kt_bh       (bh = zoff + blockIdx.z; C into local chunk)
// MODE 2: o   = p_bh @ v_bh        (epilogue writes g_att concat layout)
// MODE 3: out = att @ W_out
// ---------------------------------------------------------------------------
#define BM 128
#define BN 128
#define BK 8
#define TM 8
#define TN 8

template<int MODE>
__global__ __launch_bounds__(256)
void gemm_k(const float* __restrict__ X, const float* __restrict__ W,
            float* __restrict__ OUT, int zoff)
{
    __shared__ float As[BK][BM];
    __shared__ float Bs[BK][BN];

    const int zl = blockIdx.z;          // local slice index within chunk
    const int zg = zoff + zl;           // global bh index
    const float* A; const float* B; int lda, ldb, K;
    if (MODE == 0)      { A = X;                           lda = EQ;    B = W;                           ldb = 3*HQ*EQ; K = EQ; }
    else if (MODE == 1) { A = g_q  + (size_t)zg*LQ*EQ;     lda = EQ;    B = g_kt + (size_t)zg*EQ*LQ;     ldb = LQ;      K = EQ; }
    else if (MODE == 2) { A = g_s  + (size_t)zl*LQ*LQ;     lda = LQ;    B = g_v  + (size_t)zg*LQ*EQ;     ldb = EQ;      K = LQ; }
    else                { A = g_att;                       lda = HQ*EQ; B = W;                           ldb = EQ;      K = HQ*EQ; }

    const int tid       = threadIdx.x;
    const int threadRow = tid / (BN/TN);   // 0..15
    const int threadCol = tid % (BN/TN);   // 0..15
    const int rowBase   = blockIdx.y * BM;
    const int colBase   = blockIdx.x * BN;

    const int innerRowA = tid / (BK/4);    // 0..127
    const int innerColA = tid % (BK/4);    // 0..1 (float4 slot)
    const int innerRowB = tid / (BN/4);    // 0..7
    const int innerColB = tid % (BN/4);    // 0..31 (float4 slot)

    float acc[TM][TN];
    #pragma unroll
    for (int i = 0; i < TM; i++)
        #pragma unroll
        for (int j = 0; j < TN; j++) acc[i][j] = 0.f;

    const float* Aptr = A + (size_t)(rowBase + innerRowA) * lda + innerColA * 4;
    const float* Bptr = B + (size_t)innerRowB * ldb + colBase + innerColB * 4;

    for (int k0 = 0; k0 < K; k0 += BK) {
        float4 a4 = *reinterpret_cast<const float4*>(Aptr + k0);
        As[innerColA*4+0][innerRowA] = a4.x;
        As[innerColA*4+1][innerRowA] = a4.y;
        As[innerColA*4+2][innerRowA] = a4.z;
        As[innerColA*4+3][innerRowA] = a4.w;
        float4 b4 = *reinterpret_cast<const float4*>(Bptr + (size_t)k0 * ldb);
        *reinterpret_cast<float4*>(&Bs[innerRowB][innerColB*4]) = b4;
        __syncthreads();

        #pragma unroll
        for (int k = 0; k < BK; k++) {
            float4 m0 = *reinterpret_cast<const float4*>(&As[k][threadRow*TM]);
            float4 m1 = *reinterpret_cast<const float4*>(&As[k][threadRow*TM+4]);
            float4 n0 = *reinterpret_cast<const float4*>(&Bs[k][threadCol*TN]);
            float4 n1 = *reinterpret_cast<const float4*>(&Bs[k][threadCol*TN+4]);
            float regM[TM] = {m0.x,m0.y,m0.z,m0.w,m1.x,m1.y,m1.z,m1.w};
            float regN[TN] = {n0.x,n0.y,n0.z,n0.w,n1.x,n1.y,n1.z,n1.w};
            #pragma unroll
            for (int i = 0; i < TM; i++)
                #pragma unroll
                for (int j = 0; j < TN; j++)
                    acc[i][j] += regM[i] * regN[j];
        }
        __syncthreads();
    }

    const int gm0 = rowBase + threadRow * TM;
    const int gn0 = colBase + threadCol * TN;

    if (MODE == 0) {
        // qkv epilogue: column gn -> (part, h, e); scatter with fused transpose.
        const float scale = 1.0f / 16.0f;      // 1/sqrt(256)
        const int part = gn0 / (HQ*EQ);
        const int c    = gn0 % (HQ*EQ);
        const int h    = c / EQ;
        const int e    = c % EQ;
        #pragma unroll
        for (int i = 0; i < TM; i++) {
            const int m = gm0 + i;
            const int b = m / LQ, l = m % LQ;
            const size_t bh = (size_t)(b*HQ + h);
            if (part == 0) {
                float* dst = g_q + (bh*LQ + l)*EQ + e;
                *reinterpret_cast<float4*>(dst)   = make_float4(acc[i][0]*scale, acc[i][1]*scale, acc[i][2]*scale, acc[i][3]*scale);
                *reinterpret_cast<float4*>(dst+4) = make_float4(acc[i][4]*scale, acc[i][5]*scale, acc[i][6]*scale, acc[i][7]*scale);
            } else if (part == 1) {
                float* dst = g_kt + (bh*EQ + e)*LQ + l;   // transposed store
                #pragma unroll
                for (int j = 0; j < TN; j++) dst[(size_t)j*LQ] = acc[i][j];
            } else {
                float* dst = g_v + (bh*LQ + l)*EQ + e;
                *reinterpret_cast<float4*>(dst)   = make_float4(acc[i][0], acc[i][1], acc[i][2], acc[i][3]);
                *reinterpret_cast<float4*>(dst+4) = make_float4(acc[i][4], acc[i][5], acc[i][6], acc[i][7]);
            }
        }
    } else if (MODE == 1) {
        float* Cb = g_s + (size_t)zl*LQ*LQ;
        #pragma unroll
        for (int i = 0; i < TM; i++) {
            float* dst = Cb + (size_t)(gm0 + i)*LQ + gn0;
            *reinterpret_cast<float4*>(dst)   = make_float4(acc[i][0], acc[i][1], acc[i][2], acc[i][3]);
            *reinterpret_cast<float4*>(dst+4) = make_float4(acc[i][4], acc[i][5], acc[i][6], acc[i][7]);
        }
    } else if (MODE == 2) {
        const int b = zg / HQ, h = zg % HQ;
        #pragma unroll
        for (int i = 0; i < TM; i++) {
            float* dst = g_att + ((size_t)(b*LQ + gm0 + i))*(HQ*EQ) + h*EQ + gn0;
            *reinterpret_cast<float4*>(dst)   = make_float4(acc[i][0], acc[i][1], acc[i][2], acc[i][3]);
            *reinterpret_cast<float4*>(dst+4) = make_float4(acc[i][4], acc[i][5], acc[i][6], acc[i][7]);
        }
    } else {
        #pragma unroll
        for (int i = 0; i < TM; i++) {
            float* dst = OUT + (size_t)(gm0 + i)*EQ + gn0;
            *reinterpret_cast<float4*>(dst)   = make_float4(acc[i][0], acc[i][1], acc[i][2], acc[i][3]);
            *reinterpret_cast<float4*>(dst+4) = make_float4(acc[i][4], acc[i][5], acc[i][6], acc[i][7]);
        }
    }
}

// ---------------------------------------------------------------------------
// Row softmax over one scores chunk: GRP*LQ rows of 2048 floats.
// One block/row, values stay in registers; single read + single write.
// ---------------------------------------------------------------------------
__global__ __launch_bounds__(256)
void softmax_k()
{
    const size_t row = blockIdx.x;
    float4* p4 = reinterpret_cast<float4*>(g_s + row * LQ);
    const int tid  = threadIdx.x;
    const int lane = tid & 31;
    const int wid  = tid >> 5;
    __shared__ float red[8];

    float4 a = p4[tid];
    float4 b = p4[tid + 256];
    float v[8] = {a.x,a.y,a.z,a.w,b.x,b.y,b.z,b.w};

    // block max
    float m = v[0];
    #pragma unroll
    for (int i = 1; i < 8; i++) m = fmaxf(m, v[i]);
    #pragma unroll
    for (int o = 16; o; o >>= 1) m = fmaxf(m, __shfl_xor_sync(0xffffffffu, m, o));
    if (lane == 0) red[wid] = m;
    __syncthreads();
    float bm = red[0];
    #pragma unroll
    for (int i = 1; i < 8; i++) bm = fmaxf(bm, red[i]);
    __syncthreads();

    // exp + block sum
    float s = 0.f;
    #pragma unroll
    for (int i = 0; i < 8; i++) { v[i] = __expf(v[i] - bm); s += v[i]; }
    #pragma unroll
    for (int o = 16; o; o >>= 1) s += __shfl_xor_sync(0xffffffffu, s, o);
    if (lane == 0) red[wid] = s;
    __syncthreads();
    float bs = 0.f;
    #pragma unroll
    for (int i = 0; i < 8; i++) bs += red[i];
    const float inv = 1.0f / bs;

    p4[tid]       = make_float4(v[0]*inv, v[1]*inv, v[2]*inv, v[3]*inv);
    p4[tid + 256] = make_float4(v[4]*inv, v[5]*inv, v[6]*inv, v[7]*inv);
}

// ---------------------------------------------------------------------------
// Launch: stream-ordered, graph-capturable, allocation-free.
// Scores buffer is reused across 4 groups of GRP bh-slices; stream order
// guarantees no races between reuse.
// ---------------------------------------------------------------------------
extern "C" void kernel_launch(void* const* d_in, const int* in_sizes, int n_in,
                              void* d_out, int out_size)
{
    const float* x    = (const float*)d_in[0];   // [4,2048,256]
    const float* Wqkv = (const float*)d_in[1];   // [256,6144]
    const float* Wout = (const float*)d_in[2];   // [2048,256]
    float* out = (float*)d_out;                  // [4,2048,256]

    // 1) QKV projection + layout scatter (q pre-scaled, k transposed)
    gemm_k<0><<<dim3((3*HQ*EQ)/BN, (BQ*LQ)/BM, 1), 256>>>(x, Wqkv, out, 0);

    // 2-4) per-group: scores gemm -> softmax -> PV gemm (scores chunk reused)
    for (int g = 0; g < (BQ*HQ)/GRP; g++) {
        const int zoff = g * GRP;
        gemm_k<1><<<dim3(LQ/BN, LQ/BM, GRP), 256>>>(nullptr, nullptr, nullptr, zoff);
        softmax_k<<<GRP*LQ, 256>>>();
        gemm_k<2><<<dim3(EQ/BN, LQ/BM, GRP), 256>>>(nullptr, nullptr, nullptr, zoff);
    }

    // 5) out = att @ W_out
    gemm_k<3><<<dim3(EQ/BN, (BQ*LQ)/BM, 1), 256>>>(nullptr, Wout, out, 0);
}

// round 5
// speedup vs baseline: 3.1474x; 3.1474x over previous
#include <cuda_runtime.h>
#include <cstdint>
#include <math.h>

#define BQ 4
#define LQ 2048
#define EQ 256
#define HQ 8
#define GRP 8      // bh-slices per scores chunk (32 total -> 4 groups)

// ---------------------------------------------------------------------------
// Scratch (allocation-free device globals, ~392 MB)
// ---------------------------------------------------------------------------
__device__ float g_q    [BQ*HQ*LQ*EQ];           // [bh][l][e], pre-scaled 1/16
__device__ float g_k    [BQ*HQ*LQ*EQ];           // [bh][l][e]
__device__ float g_vt   [BQ*HQ*EQ*LQ];           // [bh][e][l] (V transposed)
__device__ float g_s    [(size_t)GRP*LQ*LQ];     // scores chunk (128 MB)
__device__ float g_att  [(size_t)BQ*LQ*HQ*EQ];   // [b][l][h*E+e]
__device__ float g_wqkvT[3*HQ*EQ*EQ];            // [6144][256]
__device__ float g_woutT[EQ*HQ*EQ];              // [256][2048]

static __device__ __forceinline__ uint32_t f2tf(float f) {
    uint32_t u; asm("cvt.rna.tf32.f32 %0, %1;" : "=r"(u) : "f"(f)); return u;
}

// ---------------------------------------------------------------------------
// tf32 mma.sync GEMM: C[M,N] = A[M,K] @ B[N,K]^T  (both K-major)
// 128x128 block, BK=32, 256 thr, 8 warps (2x4), warp tile 64x32,
// m16n8k8 fragments, register-staged double-buffered smem.
// MODE 0: qkv = x @ WqkvT^T   (epilogue scatters q*1/16 / k / v^T)
// MODE 1: s   = q_bh @ k_bh^T (z = zoff+blockIdx.z -> scores chunk slice)
// MODE 2: o   = p_bh @ vt_bh^T (epilogue writes g_att concat layout)
// MODE 3: out = att @ WoutT^T
// ---------------------------------------------------------------------------
#define BMT 128
#define BNT 128
#define BKT 32
#define SST 36                 // smem row stride (floats): 144B, 16B aligned
#define STAGE (128*SST)        // floats per stage

#define MMA_TF32(c, af, bf)                                                   \
    asm volatile("mma.sync.aligned.m16n8k8.row.col.f32.tf32.tf32.f32 "        \
        "{%0,%1,%2,%3}, {%4,%5,%6,%7}, {%8,%9}, {%0,%1,%2,%3};"               \
        : "+f"((c)[0]), "+f"((c)[1]), "+f"((c)[2]), "+f"((c)[3])              \
        : "r"((af)[0]), "r"((af)[1]), "r"((af)[2]), "r"((af)[3]),             \
          "r"((bf)[0]), "r"((bf)[1]))

template<int MODE>
__global__ void __launch_bounds__(256)
tgemm(const float* __restrict__ X, float* __restrict__ OUT, int zoff)
{
    extern __shared__ float sm[];
    float* As = sm;                 // 2 stages x 128 x SST
    float* Bs = sm + 2*STAGE;

    const int zl = blockIdx.z, zg = zoff + zl;
    const float* A; const float* B; int lda, ldb, K;
    if (MODE == 0)      { A = X;                        lda = EQ;    B = g_wqkvT;                 ldb = EQ;    K = EQ; }
    else if (MODE == 1) { A = g_q + (size_t)zg*LQ*EQ;   lda = EQ;    B = g_k  + (size_t)zg*LQ*EQ; ldb = EQ;    K = EQ; }
    else if (MODE == 2) { A = g_s + (size_t)zl*LQ*LQ;   lda = LQ;    B = g_vt + (size_t)zg*EQ*LQ; ldb = LQ;    K = LQ; }
    else                { A = g_att;                    lda = HQ*EQ; B = g_woutT;                 ldb = HQ*EQ; K = HQ*EQ; }

    const int tid  = threadIdx.x;
    const int rowBase = blockIdx.y * BMT;
    const int colBase = blockIdx.x * BNT;

    // global loader mapping: 4 float4 each for A and B
    const int lrow  = tid >> 3;     // 0..31
    const int lslot = tid & 7;      // float4 slot (0..7) -> col lslot*4
    const float* Ag = A + (size_t)(rowBase + lrow) * lda + lslot * 4;
    const float* Bg = B + (size_t)(colBase + lrow) * ldb + lslot * 4;

    // warp/fragment mapping
    const int wid  = tid >> 5, lane = tid & 31;
    const int grp  = lane >> 2, tig = lane & 3;
    const int wm   = (wid >> 2) * 64;      // 0 or 64
    const int wn   = (wid & 3) * 32;       // 0,32,64,96

    float c[4][4][4];
    #pragma unroll
    for (int mt = 0; mt < 4; mt++)
        #pragma unroll
        for (int nt = 0; nt < 4; nt++)
            #pragma unroll
            for (int i = 0; i < 4; i++) c[mt][nt][i] = 0.f;

    float4 ra[4], rb[4];
    const int nk = K / BKT;

    auto gload = [&](int kt) {
        const int k0 = kt * BKT;
        #pragma unroll
        for (int i = 0; i < 4; i++) {
            ra[i] = *reinterpret_cast<const float4*>(Ag + (size_t)(32*i) * lda + k0);
            rb[i] = *reinterpret_cast<const float4*>(Bg + (size_t)(32*i) * ldb + k0);
        }
    };
    auto sstore = [&](int st) {
        float* as = As + st*STAGE;
        float* bs = Bs + st*STAGE;
        #pragma unroll
        for (int i = 0; i < 4; i++) {
            const int idx = (lrow + 32*i) * SST + lslot * 4;
            uint4 av = make_uint4(f2tf(ra[i].x), f2tf(ra[i].y), f2tf(ra[i].z), f2tf(ra[i].w));
            uint4 bv = make_uint4(f2tf(rb[i].x), f2tf(rb[i].y), f2tf(rb[i].z), f2tf(rb[i].w));
            *reinterpret_cast<uint4*>(as + idx) = av;
            *reinterpret_cast<uint4*>(bs + idx) = bv;
        }
    };
    auto compute = [&](int st) {
        const float* as = As + st*STAGE;
        const float* bs = Bs + st*STAGE;
        #pragma unroll
        for (int ks = 0; ks < 4; ks++) {
            const int k0 = ks * 8;
            uint32_t af[4][4];
            #pragma unroll
            for (int mt = 0; mt < 4; mt++) {
                const int row = wm + mt*16 + grp;
                af[mt][0] = __float_as_uint(as[(row    )*SST + k0 + tig    ]);
                af[mt][1] = __float_as_uint(as[(row + 8)*SST + k0 + tig    ]);
                af[mt][2] = __float_as_uint(as[(row    )*SST + k0 + tig + 4]);
                af[mt][3] = __float_as_uint(as[(row + 8)*SST + k0 + tig + 4]);
            }
            uint32_t bf[4][2];
            #pragma unroll
            for (int nt = 0; nt < 4; nt++) {
                const int col = wn + nt*8 + grp;
                bf[nt][0] = __float_as_uint(bs[col*SST + k0 + tig    ]);
                bf[nt][1] = __float_as_uint(bs[col*SST + k0 + tig + 4]);
            }
            #pragma unroll
            for (int mt = 0; mt < 4; mt++)
                #pragma unroll
                for (int nt = 0; nt < 4; nt++)
                    MMA_TF32(c[mt][nt], af[mt], bf[nt]);
        }
    };

    gload(0);
    sstore(0);
    __syncthreads();

    for (int kt = 0; kt < nk; kt++) {
        if (kt + 1 < nk) gload(kt + 1);
        compute(kt & 1);
        __syncthreads();
        if (kt + 1 < nk) {
            sstore((kt + 1) & 1);
            __syncthreads();
        }
    }

    // -------------------- epilogue from fragments --------------------
    #pragma unroll
    for (int mt = 0; mt < 4; mt++) {
        #pragma unroll
        for (int nt = 0; nt < 4; nt++) {
            const int row0 = rowBase + wm + mt*16 + grp;  // and row0+8
            const int cloc = wn + nt*8 + tig*2;           // local col (and +1)
            const float* cc = c[mt][nt];

            if (MODE == 0) {
                const int part = colBase / (HQ*EQ);
                const int h    = (colBase % (HQ*EQ)) / EQ;
                const int e    = (colBase & (EQ-1)) + cloc;
                #pragma unroll
                for (int half = 0; half < 2; half++) {
                    const int m = row0 + half*8;
                    const int b = m >> 11, ltok = m & (LQ-1);
                    const size_t bh = (size_t)(b*HQ + h);
                    const float v0 = cc[half*2], v1 = cc[half*2+1];
                    if (part == 0) {
                        float2* dst = reinterpret_cast<float2*>(g_q + (bh*LQ + ltok)*EQ + e);
                        *dst = make_float2(v0 * 0.0625f, v1 * 0.0625f);
                    } else if (part == 1) {
                        float2* dst = reinterpret_cast<float2*>(g_k + (bh*LQ + ltok)*EQ + e);
                        *dst = make_float2(v0, v1);
                    } else {
                        g_vt[((size_t)bh*EQ + e    )*LQ + ltok] = v0;
                        g_vt[((size_t)bh*EQ + e + 1)*LQ + ltok] = v1;
                    }
                }
            } else if (MODE == 1) {
                const int col = colBase + cloc;
                float* base = g_s + (size_t)zl*LQ*LQ;
                *reinterpret_cast<float2*>(base + (size_t)row0*LQ + col)     = make_float2(cc[0], cc[1]);
                *reinterpret_cast<float2*>(base + (size_t)(row0+8)*LQ + col) = make_float2(cc[2], cc[3]);
            } else if (MODE == 2) {
                const int b = zg / HQ, h = zg % HQ;
                const int col = h*EQ + colBase + cloc;
                *reinterpret_cast<float2*>(g_att + (size_t)(b*LQ + row0)*(HQ*EQ) + col)     = make_float2(cc[0], cc[1]);
                *reinterpret_cast<float2*>(g_att + (size_t)(b*LQ + row0 + 8)*(HQ*EQ) + col) = make_float2(cc[2], cc[3]);
            } else {
                const int col = colBase + cloc;
                *reinterpret_cast<float2*>(OUT + (size_t)row0*EQ + col)     = make_float2(cc[0], cc[1]);
                *reinterpret_cast<float2*>(OUT + (size_t)(row0+8)*EQ + col) = make_float2(cc[2], cc[3]);
            }
        }
    }
}

// ---------------------------------------------------------------------------
// Weight transposes (tiny, once per invocation)
// ---------------------------------------------------------------------------
template<int WM>
__global__ void __launch_bounds__(256) transpose_k(const float* __restrict__ src)
{
    constexpr int R = (WM == 0) ? EQ : HQ*EQ;       // src rows
    constexpr int C = (WM == 0) ? 3*HQ*EQ : EQ;     // src cols
    float* dst = (WM == 0) ? g_wqkvT : g_woutT;     // [C][R]
    __shared__ float t[32][33];
    const int c0 = blockIdx.x * 32, r0 = blockIdx.y * 32;
    const int tx = threadIdx.x & 31, ty = threadIdx.x >> 5;
    #pragma unroll
    for (int i = 0; i < 4; i++)
        t[ty + i*8][tx] = src[(size_t)(r0 + ty + i*8) * C + c0 + tx];
    __syncthreads();
    #pragma unroll
    for (int i = 0; i < 4; i++)
        dst[(size_t)(c0 + ty + i*8) * R + r0 + tx] = t[tx][ty + i*8];
}

// ---------------------------------------------------------------------------
// Row softmax over one scores chunk: GRP*LQ rows of 2048 floats (registers)
// ---------------------------------------------------------------------------
__global__ __launch_bounds__(256)
void softmax_k()
{
    const size_t row = blockIdx.x;
    float4* p4 = reinterpret_cast<float4*>(g_s + row * LQ);
    const int tid = threadIdx.x, lane = tid & 31, wid = tid >> 5;
    __shared__ float red[8];

    float4 a = p4[tid];
    float4 b = p4[tid + 256];
    float v[8] = {a.x, a.y, a.z, a.w, b.x, b.y, b.z, b.w};

    float m = v[0];
    #pragma unroll
    for (int i = 1; i < 8; i++) m = fmaxf(m, v[i]);
    #pragma unroll
    for (int o = 16; o; o >>= 1) m = fmaxf(m, __shfl_xor_sync(0xffffffffu, m, o));
    if (lane == 0) red[wid] = m;
    __syncthreads();
    float bm = red[0];
    #pragma unroll
    for (int i = 1; i < 8; i++) bm = fmaxf(bm, red[i]);
    __syncthreads();

    float s = 0.f;
    #pragma unroll
    for (int i = 0; i < 8; i++) { v[i] = __expf(v[i] - bm); s += v[i]; }
    #pragma unroll
    for (int o = 16; o; o >>= 1) s += __shfl_xor_sync(0xffffffffu, s, o);
    if (lane == 0) red[wid] = s;
    __syncthreads();
    float bs = 0.f;
    #pragma unroll
    for (int i = 0; i < 8; i++) bs += red[i];
    const float inv = 1.0f / bs;

    p4[tid]       = make_float4(v[0]*inv, v[1]*inv, v[2]*inv, v[3]*inv);
    p4[tid + 256] = make_float4(v[4]*inv, v[5]*inv, v[6]*inv, v[7]*inv);
}

// ---------------------------------------------------------------------------
// Launch: stream-ordered, graph-capturable, allocation-free
// ---------------------------------------------------------------------------
#define TG_SMEM (4 * STAGE * (int)sizeof(float))   // 73728 bytes

extern "C" void kernel_launch(void* const* d_in, const int* in_sizes, int n_in,
                              void* d_out, int out_size)
{
    const float* x    = (const float*)d_in[0];   // [4,2048,256]
    const float* Wqkv = (const float*)d_in[1];   // [256,6144]
    const float* Wout = (const float*)d_in[2];   // [2048,256]
    float* out = (float*)d_out;                  // [4,2048,256]

    cudaFuncSetAttribute(tgemm<0>, cudaFuncAttributeMaxDynamicSharedMemorySize, TG_SMEM);
    cudaFuncSetAttribute(tgemm<1>, cudaFuncAttributeMaxDynamicSharedMemorySize, TG_SMEM);
    cudaFuncSetAttribute(tgemm<2>, cudaFuncAttributeMaxDynamicSharedMemorySize, TG_SMEM);
    cudaFuncSetAttribute(tgemm<3>, cudaFuncAttributeMaxDynamicSharedMemorySize, TG_SMEM);

    transpose_k<0><<<dim3((3*HQ*EQ)/32, EQ/32), 256>>>(Wqkv);
    transpose_k<1><<<dim3(EQ/32, (HQ*EQ)/32), 256>>>(Wout);

    // 1) QKV projection (tf32 mma) + scatter: q scaled, k natural, v^T
    tgemm<0><<<dim3((3*HQ*EQ)/BNT, (BQ*LQ)/BMT, 1), 256, TG_SMEM>>>(x, nullptr, 0);

    // 2-4) per-group attention: scores -> softmax -> PV
    for (int g = 0; g < (BQ*HQ)/GRP; g++) {
        const int zoff = g * GRP;
        tgemm<1><<<dim3(LQ/BNT, LQ/BMT, GRP), 256, TG_SMEM>>>(nullptr, nullptr, zoff);
        softmax_k<<<GRP*LQ, 256>>>();
        tgemm<2><<<dim3(EQ/BNT, LQ/BMT, GRP), 256, TG_SMEM>>>(nullptr, nullptr, zoff);
    }

    // 5) out = att @ W_out
    tgemm<3><<<dim3(EQ/BNT, (BQ*LQ)/BMT, 1), 256, TG_SMEM>>>(nullptr, out, 0);
}

// round 6
// speedup vs baseline: 4.8905x; 1.5538x over previous
#include <cuda_runtime.h>
#include <cuda_fp16.h>
#include <cstdint>
#include <math.h>

#define BQ 4
#define LQ 2048
#define EQ 256
#define HQ 8
#define GRP 8      // bh-slices per scores chunk (32 total -> 4 groups)

// ---------------------------------------------------------------------------
// Scratch (allocation-free device globals)
// ---------------------------------------------------------------------------
__device__ __half g_xh   [BQ*LQ*EQ];              // x in fp16
__device__ __half g_qh   [BQ*HQ*LQ*EQ];           // [bh][l][e], pre-scaled 1/16
__device__ __half g_kh   [BQ*HQ*LQ*EQ];           // [bh][l][e]
__device__ __half g_vth  [BQ*HQ*EQ*LQ];           // [bh][e][l] (V transposed)
__device__ float  g_s    [(size_t)GRP*LQ*LQ];     // fp32 scores chunk (128 MB)
__device__ __half g_p    [(size_t)GRP*LQ*LQ];     // fp16 probabilities (64 MB)
__device__ __half g_atth [(size_t)BQ*LQ*HQ*EQ];   // [b][l][h*E+e]
__device__ __half g_wqkvTh[3*HQ*EQ*EQ];           // [6144][256]
__device__ __half g_woutTh[EQ*HQ*EQ];             // [256][2048]

static __device__ __forceinline__ uint32_t smem_u32(const void* p) {
    uint32_t a;
    asm("{ .reg .u64 t; cvta.to.shared.u64 t, %1; cvt.u32.u64 %0, t; }" : "=r"(a) : "l"(p));
    return a;
}
#define CP_ASYNC16(d, s) \
    asm volatile("cp.async.cg.shared.global [%0], [%1], 16;" :: "r"(d), "l"(s))
#define CP_COMMIT() asm volatile("cp.async.commit_group;" ::: "memory")
template<int N> static __device__ __forceinline__ void cp_wait() {
    asm volatile("cp.async.wait_group %0;" :: "n"(N) : "memory");
}

#define MMA_F16(c, af, bf)                                                    \
    asm volatile("mma.sync.aligned.m16n8k16.row.col.f32.f16.f16.f32 "         \
        "{%0,%1,%2,%3}, {%4,%5,%6,%7}, {%8,%9}, {%0,%1,%2,%3};"               \
        : "+f"((c)[0]), "+f"((c)[1]), "+f"((c)[2]), "+f"((c)[3])              \
        : "r"((af)[0]), "r"((af)[1]), "r"((af)[2]), "r"((af)[3]),             \
          "r"((bf)[0]), "r"((bf)[1]))

// ---------------------------------------------------------------------------
// fp16 mma.sync GEMM: C[M,N] = A[M,K] @ B[N,K]^T  (both K-major fp16)
// 128x128 block, BK=32, 256 thr, 8 warps (2x4), warp tile 64x32, m16n8k16,
// cp.async double-buffered smem.
// MODE 0: qkv = xh @ WqkvTh^T  (epilogue scatters q*1/16 / k / v^T, fp16)
// MODE 1: s   = q_bh @ k_bh^T  -> fp32 scores chunk
// MODE 2: o   = p_bh @ vt_bh^T -> g_atth concat layout (fp16)
// MODE 3: out = att @ WoutTh^T -> fp32 output
// ---------------------------------------------------------------------------
#define BMT 128
#define BNT 128
#define BKT 32
#define SSTH 40                    // smem row stride in halves (80B, 16B-aligned)
#define ASTAGE (128*SSTH)          // halves per operand-stage (5120)

template<int MODE>
__global__ void __launch_bounds__(256)
tgemm(float* __restrict__ OUT, int zoff)
{
    __shared__ __align__(16) __half smh[4 * ASTAGE];   // As0,As1,Bs0,Bs1 (40 KB)

    const int zl = blockIdx.z, zg = zoff + zl;
    const __half* A; const __half* B; int lda, ldb, K;
    if (MODE == 0)      { A = g_xh;                      lda = EQ;    B = g_wqkvTh;                 ldb = EQ;    K = EQ; }
    else if (MODE == 1) { A = g_qh + (size_t)zg*LQ*EQ;   lda = EQ;    B = g_kh  + (size_t)zg*LQ*EQ; ldb = EQ;    K = EQ; }
    else if (MODE == 2) { A = g_p  + (size_t)zl*LQ*LQ;   lda = LQ;    B = g_vth + (size_t)zg*EQ*LQ; ldb = LQ;    K = LQ; }
    else                { A = g_atth;                    lda = HQ*EQ; B = g_woutTh;                 ldb = HQ*EQ; K = HQ*EQ; }

    const int tid  = threadIdx.x;
    const int rowBase = blockIdx.y * BMT;
    const int colBase = blockIdx.x * BNT;

    // cp.async loader mapping: rows lrow & lrow+64, 8-half (16B) slot lslot
    const int lrow  = tid >> 2;     // 0..63
    const int lslot = tid & 3;      // 0..3
    const __half* Agp = A + (size_t)(rowBase + lrow) * lda + lslot * 8;
    const __half* Bgp = B + (size_t)(colBase + lrow) * ldb + lslot * 8;
    const uint32_t sbase = smem_u32(smh);
    const uint32_t soffA = (uint32_t)(lrow * SSTH + lslot * 8) * 2;
    // warp/fragment mapping
    const int wid  = tid >> 5, lane = tid & 31;
    const int grp  = lane >> 2, tig = lane & 3;
    const int wm   = (wid >> 2) * 64;      // 0 or 64
    const int wn   = (wid & 3) * 32;       // 0,32,64,96

    float c[4][4][4];
    #pragma unroll
    for (int mt = 0; mt < 4; mt++)
        #pragma unroll
        for (int nt = 0; nt < 4; nt++)
            #pragma unroll
            for (int i = 0; i < 4; i++) c[mt][nt][i] = 0.f;

    const int nk = K / BKT;

    auto issue = [&](int kt, int st) {
        const int k0 = kt * BKT;
        const uint32_t dA = sbase + st * (ASTAGE*2) + soffA;
        const uint32_t dB = dA + 2 * (ASTAGE*2);
        CP_ASYNC16(dA,                 Agp + k0);
        CP_ASYNC16(dA + 64*SSTH*2,     Agp + k0 + (size_t)64*lda);
        CP_ASYNC16(dB,                 Bgp + k0);
        CP_ASYNC16(dB + 64*SSTH*2,     Bgp + k0 + (size_t)64*ldb);
    };
    auto compute = [&](int st) {
        const __half* as = smh + st*ASTAGE;
        const __half* bs = smh + 2*ASTAGE + st*ASTAGE;
        #pragma unroll
        for (int ks = 0; ks < 2; ks++) {
            const int k0 = ks * 16;
            uint32_t af[4][4];
            #pragma unroll
            for (int mt = 0; mt < 4; mt++) {
                const int row = wm + mt*16 + grp;
                af[mt][0] = *reinterpret_cast<const uint32_t*>(as + (row    )*SSTH + k0 + 2*tig    );
                af[mt][1] = *reinterpret_cast<const uint32_t*>(as + (row + 8)*SSTH + k0 + 2*tig    );
                af[mt][2] = *reinterpret_cast<const uint32_t*>(as + (row    )*SSTH + k0 + 2*tig + 8);
                af[mt][3] = *reinterpret_cast<const uint32_t*>(as + (row + 8)*SSTH + k0 + 2*tig + 8);
            }
            uint32_t bf[4][2];
            #pragma unroll
            for (int nt = 0; nt < 4; nt++) {
                const int col = wn + nt*8 + grp;
                bf[nt][0] = *reinterpret_cast<const uint32_t*>(bs + col*SSTH + k0 + 2*tig    );
                bf[nt][1] = *reinterpret_cast<const uint32_t*>(bs + col*SSTH + k0 + 2*tig + 8);
            }
            #pragma unroll
            for (int mt = 0; mt < 4; mt++)
                #pragma unroll
                for (int nt = 0; nt < 4; nt++)
                    MMA_F16(c[mt][nt], af[mt], bf[nt]);
        }
    };

    issue(0, 0);
    CP_COMMIT();
    for (int kt = 0; kt < nk; kt++) {
        if (kt + 1 < nk) {
            issue(kt + 1, (kt + 1) & 1);
            CP_COMMIT();
            cp_wait<1>();
        } else {
            cp_wait<0>();
        }
        __syncthreads();
        compute(kt & 1);
        __syncthreads();
    }

    // -------------------- epilogue from fragments --------------------
    #pragma unroll
    for (int mt = 0; mt < 4; mt++) {
        #pragma unroll
        for (int nt = 0; nt < 4; nt++) {
            const int row0 = rowBase + wm + mt*16 + grp;  // and row0+8
            const int cloc = wn + nt*8 + tig*2;           // local col (and +1)
            const float* cc = c[mt][nt];

            if (MODE == 0) {
                const int part = colBase / (HQ*EQ);
                const int h    = (colBase % (HQ*EQ)) / EQ;
                const int e    = (colBase & (EQ-1)) + cloc;
                #pragma unroll
                for (int half = 0; half < 2; half++) {
                    const int m = row0 + half*8;
                    const int b = m >> 11, ltok = m & (LQ-1);
                    const size_t bh = (size_t)(b*HQ + h);
                    const float v0 = cc[half*2], v1 = cc[half*2+1];
                    if (part == 0) {
                        *reinterpret_cast<__half2*>(g_qh + (bh*LQ + ltok)*EQ + e) =
                            __floats2half2_rn(v0 * 0.0625f, v1 * 0.0625f);
                    } else if (part == 1) {
                        *reinterpret_cast<__half2*>(g_kh + (bh*LQ + ltok)*EQ + e) =
                            __floats2half2_rn(v0, v1);
                    } else {
                        g_vth[((size_t)bh*EQ + e    )*LQ + ltok] = __float2half_rn(v0);
                        g_vth[((size_t)bh*EQ + e + 1)*LQ + ltok] = __float2half_rn(v1);
                    }
                }
            } else if (MODE == 1) {
                const int col = colBase + cloc;
                float* base = g_s + (size_t)zl*LQ*LQ;
                *reinterpret_cast<float2*>(base + (size_t)row0*LQ + col)     = make_float2(cc[0], cc[1]);
                *reinterpret_cast<float2*>(base + (size_t)(row0+8)*LQ + col) = make_float2(cc[2], cc[3]);
            } else if (MODE == 2) {
                const int b = zg / HQ, h = zg % HQ;
                const int col = h*EQ + colBase + cloc;
                *reinterpret_cast<__half2*>(g_atth + (size_t)(b*LQ + row0)*(HQ*EQ) + col) =
                    __floats2half2_rn(cc[0], cc[1]);
                *reinterpret_cast<__half2*>(g_atth + (size_t)(b*LQ + row0 + 8)*(HQ*EQ) + col) =
                    __floats2half2_rn(cc[2], cc[3]);
            } else {
                const int col = colBase + cloc;
                *reinterpret_cast<float2*>(OUT + (size_t)row0*EQ + col)     = make_float2(cc[0], cc[1]);
                *reinterpret_cast<float2*>(OUT + (size_t)(row0+8)*EQ + col) = make_float2(cc[2], cc[3]);
            }
        }
    }
}

// ---------------------------------------------------------------------------
// x -> fp16 (elementwise, vectorized)
// ---------------------------------------------------------------------------
__global__ void __launch_bounds__(256) conv_x_k(const float* __restrict__ x)
{
    const int i = blockIdx.x * 256 + threadIdx.x;     // float4 index
    float4 v = reinterpret_cast<const float4*>(x)[i];
    __half2* o = reinterpret_cast<__half2*>(g_xh);
    o[2*i]   = __floats2half2_rn(v.x, v.y);
    o[2*i+1] = __floats2half2_rn(v.z, v.w);
}

// ---------------------------------------------------------------------------
// Weight transpose + fp16 convert (tiny)
// ---------------------------------------------------------------------------
template<int WM>
__global__ void __launch_bounds__(256) transpose_k(const float* __restrict__ src)
{
    constexpr int R = (WM == 0) ? EQ : HQ*EQ;       // src rows
    constexpr int C = (WM == 0) ? 3*HQ*EQ : EQ;     // src cols
    __half* dst = (WM == 0) ? g_wqkvTh : g_woutTh;  // [C][R]
    __shared__ float t[32][33];
    const int c0 = blockIdx.x * 32, r0 = blockIdx.y * 32;
    const int tx = threadIdx.x & 31, ty = threadIdx.x >> 5;
    #pragma unroll
    for (int i = 0; i < 4; i++)
        t[ty + i*8][tx] = src[(size_t)(r0 + ty + i*8) * C + c0 + tx];
    __syncthreads();
    #pragma unroll
    for (int i = 0; i < 4; i++)
        dst[(size_t)(c0 + ty + i*8) * R + r0 + tx] = __float2half_rn(t[tx][ty + i*8]);
}

// ---------------------------------------------------------------------------
// Row softmax: reads fp32 scores chunk, writes fp16 probabilities
// ---------------------------------------------------------------------------
__global__ __launch_bounds__(256)
void softmax_k()
{
    const size_t row = blockIdx.x;
    const float4* p4 = reinterpret_cast<const float4*>(g_s + row * LQ);
    __half2* o2 = reinterpret_cast<__half2*>(g_p + row * LQ);
    const int tid = threadIdx.x, lane = tid & 31, wid = tid >> 5;
    __shared__ float red[8];

    float4 a = p4[tid];
    float4 b = p4[tid + 256];
    float v[8] = {a.x, a.y, a.z, a.w, b.x, b.y, b.z, b.w};

    float m = v[0];
    #pragma unroll
    for (int i = 1; i < 8; i++) m = fmaxf(m, v[i]);
    #pragma unroll
    for (int o = 16; o; o >>= 1) m = fmaxf(m, __shfl_xor_sync(0xffffffffu, m, o));
    if (lane == 0) red[wid] = m;
    __syncthreads();
    float bm = red[0];
    #pragma unroll
    for (int i = 1; i < 8; i++) bm = fmaxf(bm, red[i]);
    __syncthreads();

    float s = 0.f;
    #pragma unroll
    for (int i = 0; i < 8; i++) { v[i] = __expf(v[i] - bm); s += v[i]; }
    #pragma unroll
    for (int o = 16; o; o >>= 1) s += __shfl_xor_sync(0xffffffffu, s, o);
    if (lane == 0) red[wid] = s;
    __syncthreads();
    float bs = 0.f;
    #pragma unroll
    for (int i = 0; i < 8; i++) bs += red[i];
    const float inv = 1.0f / bs;

    o2[2*tid]       = __floats2half2_rn(v[0]*inv, v[1]*inv);
    o2[2*tid+1]     = __floats2half2_rn(v[2]*inv, v[3]*inv);
    o2[512 + 2*tid] = __floats2half2_rn(v[4]*inv, v[5]*inv);
    o2[513 + 2*tid] = __floats2half2_rn(v[6]*inv, v[7]*inv);
}

// ---------------------------------------------------------------------------
// Launch: stream-ordered, graph-capturable, allocation-free
// ---------------------------------------------------------------------------
extern "C" void kernel_launch(void* const* d_in, const int* in_sizes, int n_in,
                              void* d_out, int out_size)
{
    const float* x    = (const float*)d_in[0];   // [4,2048,256]
    const float* Wqkv = (const float*)d_in[1];   // [256,6144]
    const float* Wout = (const float*)d_in[2];   // [2048,256]
    float* out = (float*)d_out;                  // [4,2048,256]

    conv_x_k<<<(BQ*LQ*EQ)/1024, 256>>>(x);
    transpose_k<0><<<dim3((3*HQ*EQ)/32, EQ/32), 256>>>(Wqkv);
    transpose_k<1><<<dim3(EQ/32, (HQ*EQ)/32), 256>>>(Wout);

    // 1) QKV projection (fp16 mma) + scatter: q scaled, k natural, v^T
    tgemm<0><<<dim3((3*HQ*EQ)/BNT, (BQ*LQ)/BMT, 1), 256>>>(nullptr, 0);

    // 2-4) per-group attention: scores -> softmax -> PV
    for (int g = 0; g < (BQ*HQ)/GRP; g++) {
        const int zoff = g * GRP;
        tgemm<1><<<dim3(LQ/BNT, LQ/BMT, GRP), 256>>>(nullptr, zoff);
        softmax_k<<<GRP*LQ, 256>>>();
        tgemm<2><<<dim3(EQ/BNT, LQ/BMT, GRP), 256>>>(nullptr, zoff);
    }

    // 5) out = att @ W_out
    tgemm<3><<<dim3(EQ/BNT, (BQ*LQ)/BMT, 1), 256>>>(out, 0);
}

// round 7
// speedup vs baseline: 5.1619x; 1.0555x over previous
#include <cuda_runtime.h>
#include <cuda_fp16.h>
#include <cstdint>
#include <math.h>

#define BQ 4
#define LQ 2048
#define EQ 256
#define HQ 8
#define GRP 8      // bh-slices per scores chunk (32 total -> 4 groups)

// ---------------------------------------------------------------------------
// Scratch (allocation-free device globals)
// ---------------------------------------------------------------------------
__device__ __half g_xh   [BQ*LQ*EQ];              // x in fp16
__device__ __half g_qh   [BQ*HQ*LQ*EQ];           // [bh][l][e], pre-scaled 1/16
__device__ __half g_kh   [BQ*HQ*LQ*EQ];           // [bh][l][e]
__device__ __half g_vth  [BQ*HQ*EQ*LQ];           // [bh][e][l] (V transposed)
__device__ float  g_s    [(size_t)GRP*LQ*LQ];     // fp32 scores chunk (128 MB)
__device__ __half g_p    [(size_t)GRP*LQ*LQ];     // fp16 probabilities (64 MB)
__device__ __half g_atth [(size_t)BQ*LQ*HQ*EQ];   // [b][l][h*E+e]
__device__ __half g_wqkvTh[3*HQ*EQ*EQ];           // [6144][256]
__device__ __half g_woutTh[EQ*HQ*EQ];             // [256][2048]

static __device__ __forceinline__ uint32_t smem_u32(const void* p) {
    uint32_t a;
    asm("{ .reg .u64 t; cvta.to.shared.u64 t, %1; cvt.u32.u64 %0, t; }" : "=r"(a) : "l"(p));
    return a;
}
#define CP_ASYNC16(d, s) \
    asm volatile("cp.async.cg.shared.global [%0], [%1], 16;" :: "r"(d), "l"(s))
#define CP_COMMIT() asm volatile("cp.async.commit_group;" ::: "memory")
template<int N> static __device__ __forceinline__ void cp_wait() {
    asm volatile("cp.async.wait_group %0;" :: "n"(N) : "memory");
}
#define LDSM4(r0, r1, r2, r3, a)                                              \
    asm volatile("ldmatrix.sync.aligned.m8n8.x4.shared.b16 {%0,%1,%2,%3}, [%4];" \
        : "=r"(r0), "=r"(r1), "=r"(r2), "=r"(r3) : "r"(a))
#define MMA_F16(c, a0, a1, a2, a3, b0, b1)                                    \
    asm volatile("mma.sync.aligned.m16n8k16.row.col.f32.f16.f16.f32 "         \
        "{%0,%1,%2,%3}, {%4,%5,%6,%7}, {%8,%9}, {%0,%1,%2,%3};"               \
        : "+f"((c)[0]), "+f"((c)[1]), "+f"((c)[2]), "+f"((c)[3])              \
        : "r"(a0), "r"(a1), "r"(a2), "r"(a3), "r"(b0), "r"(b1))

// ---------------------------------------------------------------------------
// fp16 mma GEMM: C[M,N] = A[M,K] @ B[N,K]^T  (both K-major fp16)
// CTA tile 128 x BNTT, BK=32, 256 thr, 8 warps (2x4), warp tile 64x(BNTT/4).
// ldmatrix fragment loads, 4-stage cp.async pipeline.
// MODE 0 (BNTT=256): qkv = xh @ WqkvTh^T   scatter q*1/16 / k / v^T
// MODE 1 (BNTT=256): s   = q @ k^T -> fp32 scores chunk
// MODE 2 (BNTT=256): o   = p @ vt^T -> g_atth concat
// MODE 3 (BNTT=128): out = att @ WoutTh^T -> fp32
// ---------------------------------------------------------------------------
#define BMT 128
#define BKT 32
#define SSTH 40                        // smem row stride in halves (80 B)
#define AS_H (128*SSTH)                // A-stage halves

template<int MODE, int BNTT>
__global__ void __launch_bounds__(256)
tgemm(float* __restrict__ OUT, int zoff)
{
    constexpr int NT2   = BNTT / 64;             // 16-col B groups per warp
    constexpr int BS_H  = BNTT * SSTH;           // B-stage halves
    constexpr int STG_B = (AS_H + BS_H) * 2;     // stage bytes

    extern __shared__ __align__(16) __half smh[];

    const int zl = blockIdx.z, zg = zoff + zl;
    const __half* A; const __half* B; int lda, ldb, K;
    if (MODE == 0)      { A = g_xh;                      lda = EQ;    B = g_wqkvTh;                 ldb = EQ;    K = EQ; }
    else if (MODE == 1) { A = g_qh + (size_t)zg*LQ*EQ;   lda = EQ;    B = g_kh  + (size_t)zg*LQ*EQ; ldb = EQ;    K = EQ; }
    else if (MODE == 2) { A = g_p  + (size_t)zl*LQ*LQ;   lda = LQ;    B = g_vth + (size_t)zg*EQ*LQ; ldb = LQ;    K = LQ; }
    else                { A = g_atth;                    lda = HQ*EQ; B = g_woutTh;                 ldb = HQ*EQ; K = HQ*EQ; }

    const int tid  = threadIdx.x;
    const int rowBase = blockIdx.y * BMT;
    const int colBase = blockIdx.x * BNTT;

    // cp.async loader mapping: thread -> (row t>>2 (+64i), 16B slot t&3)
    const int lrow  = tid >> 2;
    const int lslot = tid & 3;
    const __half* Ag = A + (size_t)(rowBase + lrow) * lda + lslot * 8;
    const __half* Bg = B + (size_t)(colBase + lrow) * ldb + lslot * 8;
    const uint32_t sbase = smem_u32(smh);
    const uint32_t soff  = (uint32_t)(lrow * SSTH + lslot * 8) * 2;

    // warp/fragment mapping
    const int wid  = tid >> 5, lane = tid & 31;
    const int grp  = lane >> 2, tig = lane & 3;
    const int wm   = (wid >> 2) * 64;            // 0 or 64
    const int wn   = (wid & 3) * (BNTT / 4);     // warp col base

    // ldmatrix lane address offsets (halves)
    const uint32_t aoffh = (uint32_t)((wm + (lane & 15)) * SSTH + ((lane >> 4) * 8));
    const uint32_t boffh = (uint32_t)((wn + (lane & 7) + ((lane & 16) >> 1)) * SSTH + (lane & 8));

    float c[4][NT2][2][4];
    #pragma unroll
    for (int mt = 0; mt < 4; mt++)
        #pragma unroll
        for (int n2 = 0; n2 < NT2; n2++)
            #pragma unroll
            for (int s = 0; s < 2; s++)
                #pragma unroll
                for (int i = 0; i < 4; i++) c[mt][n2][s][i] = 0.f;

    const int nk = K / BKT;

    auto issue = [&](int kt, int st) {
        const int k0 = kt * BKT;
        const uint32_t dA = sbase + st * STG_B + soff;
        CP_ASYNC16(dA,                Ag + k0);
        CP_ASYNC16(dA + 2*64*SSTH,    Ag + k0 + (size_t)64 * lda);
        const uint32_t dB = sbase + st * STG_B + 2*AS_H + soff;
        #pragma unroll
        for (int i = 0; i < BNTT/64; i++)
            CP_ASYNC16(dB + i*2*64*SSTH, Bg + k0 + (size_t)(64*i) * ldb);
    };
    auto compute = [&](int st) {
        const uint32_t ab = sbase + st * STG_B + 2*aoffh;
        const uint32_t bb = sbase + st * STG_B + 2*AS_H + 2*boffh;
        #pragma unroll
        for (int ks = 0; ks < 2; ks++) {
            uint32_t af[4][4];
            #pragma unroll
            for (int mt = 0; mt < 4; mt++)
                LDSM4(af[mt][0], af[mt][1], af[mt][2], af[mt][3],
                      ab + 2*(uint32_t)(mt*16*SSTH + ks*16));
            #pragma unroll
            for (int n2 = 0; n2 < NT2; n2++) {
                uint32_t b0, b1, b2, b3;
                LDSM4(b0, b1, b2, b3, bb + 2*(uint32_t)(n2*16*SSTH + ks*16));
                #pragma unroll
                for (int mt = 0; mt < 4; mt++) {
                    MMA_F16(c[mt][n2][0], af[mt][0], af[mt][1], af[mt][2], af[mt][3], b0, b1);
                    MMA_F16(c[mt][n2][1], af[mt][0], af[mt][1], af[mt][2], af[mt][3], b2, b3);
                }
            }
        }
    };

    #pragma unroll
    for (int s = 0; s < 3; s++) { issue(s, s); CP_COMMIT(); }
    for (int kt = 0; kt < nk; kt++) {
        cp_wait<2>();
        __syncthreads();
        if (kt + 3 < nk) issue(kt + 3, (kt + 3) & 3);
        CP_COMMIT();
        compute(kt & 3);
    }

    // -------------------- epilogue from fragments --------------------
    #pragma unroll
    for (int mt = 0; mt < 4; mt++) {
        #pragma unroll
        for (int n2 = 0; n2 < NT2; n2++) {
            #pragma unroll
            for (int s = 0; s < 2; s++) {
                const int row0 = rowBase + wm + mt*16 + grp;   // and +8
                const int cloc = wn + (n2*2 + s)*8 + tig*2;    // local col (and +1)
                const float* cc = c[mt][n2][s];

                if (MODE == 0) {
                    const int part = colBase >> 11;
                    const int h    = (colBase >> 8) & 7;
                    const int e    = cloc;
                    #pragma unroll
                    for (int hh = 0; hh < 2; hh++) {
                        const int m = row0 + hh*8;
                        const int b = m >> 11, ltok = m & (LQ-1);
                        const size_t bh = (size_t)(b*HQ + h);
                        const float v0 = cc[hh*2], v1 = cc[hh*2+1];
                        if (part == 0) {
                            *reinterpret_cast<__half2*>(g_qh + (bh*LQ + ltok)*EQ + e) =
                                __floats2half2_rn(v0 * 0.0625f, v1 * 0.0625f);
                        } else if (part == 1) {
                            *reinterpret_cast<__half2*>(g_kh + (bh*LQ + ltok)*EQ + e) =
                                __floats2half2_rn(v0, v1);
                        } else {
                            g_vth[((size_t)bh*EQ + e    )*LQ + ltok] = __float2half_rn(v0);
                            g_vth[((size_t)bh*EQ + e + 1)*LQ + ltok] = __float2half_rn(v1);
                        }
                    }
                } else if (MODE == 1) {
                    const int col = colBase + cloc;
                    float* base = g_s + (size_t)zl*LQ*LQ;
                    *reinterpret_cast<float2*>(base + (size_t)row0*LQ + col)     = make_float2(cc[0], cc[1]);
                    *reinterpret_cast<float2*>(base + (size_t)(row0+8)*LQ + col) = make_float2(cc[2], cc[3]);
                } else if (MODE == 2) {
                    const int b = zg / HQ, h = zg % HQ;
                    const int col = h*EQ + cloc;
                    *reinterpret_cast<__half2*>(g_atth + (size_t)(b*LQ + row0)*(HQ*EQ) + col) =
                        __floats2half2_rn(cc[0], cc[1]);
                    *reinterpret_cast<__half2*>(g_atth + (size_t)(b*LQ + row0 + 8)*(HQ*EQ) + col) =
                        __floats2half2_rn(cc[2], cc[3]);
                } else {
                    const int col = colBase + cloc;
                    *reinterpret_cast<float2*>(OUT + (size_t)row0*EQ + col)     = make_float2(cc[0], cc[1]);
                    *reinterpret_cast<float2*>(OUT + (size_t)(row0+8)*EQ + col) = make_float2(cc[2], cc[3]);
                }
            }
        }
    }
}

// ---------------------------------------------------------------------------
// x -> fp16 (elementwise, vectorized)
// ---------------------------------------------------------------------------
__global__ void __launch_bounds__(256) conv_x_k(const float* __restrict__ x)
{
    const int i = blockIdx.x * 256 + threadIdx.x;     // float4 index
    float4 v = reinterpret_cast<const float4*>(x)[i];
    __half2* o = reinterpret_cast<__half2*>(g_xh);
    o[2*i]   = __floats2half2_rn(v.x, v.y);
    o[2*i+1] = __floats2half2_rn(v.z, v.w);
}

// ---------------------------------------------------------------------------
// Weight transpose + fp16 convert (tiny)
// ---------------------------------------------------------------------------
template<int WM>
__global__ void __launch_bounds__(256) transpose_k(const float* __restrict__ src)
{
    constexpr int R = (WM == 0) ? EQ : HQ*EQ;
    constexpr int C = (WM == 0) ? 3*HQ*EQ : EQ;
    __half* dst = (WM == 0) ? g_wqkvTh : g_woutTh;
    __shared__ float t[32][33];
    const int c0 = blockIdx.x * 32, r0 = blockIdx.y * 32;
    const int tx = threadIdx.x & 31, ty = threadIdx.x >> 5;
    #pragma unroll
    for (int i = 0; i < 4; i++)
        t[ty + i*8][tx] = src[(size_t)(r0 + ty + i*8) * C + c0 + tx];
    __syncthreads();
    #pragma unroll
    for (int i = 0; i < 4; i++)
        dst[(size_t)(c0 + ty + i*8) * R + r0 + tx] = __float2half_rn(t[tx][ty + i*8]);
}

// ---------------------------------------------------------------------------
// Row softmax: fp32 scores -> fp16 probabilities
// ---------------------------------------------------------------------------
__global__ __launch_bounds__(256)
void softmax_k()
{
    const size_t row = blockIdx.x;
    const float4* p4 = reinterpret_cast<const float4*>(g_s + row * LQ);
    __half2* o2 = reinterpret_cast<__half2*>(g_p + row * LQ);
    const int tid = threadIdx.x, lane = tid & 31, wid = tid >> 5;
    __shared__ float red[8];

    float4 a = p4[tid];
    float4 b = p4[tid + 256];
    float v[8] = {a.x, a.y, a.z, a.w, b.x, b.y, b.z, b.w};

    float m = v[0];
    #pragma unroll
    for (int i = 1; i < 8; i++) m = fmaxf(m, v[i]);
    #pragma unroll
    for (int o = 16; o; o >>= 1) m = fmaxf(m, __shfl_xor_sync(0xffffffffu, m, o));
    if (lane == 0) red[wid] = m;
    __syncthreads();
    float bm = red[0];
    #pragma unroll
    for (int i = 1; i < 8; i++) bm = fmaxf(bm, red[i]);
    __syncthreads();

    float s = 0.f;
    #pragma unroll
    for (int i = 0; i < 8; i++) { v[i] = __expf(v[i] - bm); s += v[i]; }
    #pragma unroll
    for (int o = 16; o; o >>= 1) s += __shfl_xor_sync(0xffffffffu, s, o);
    if (lane == 0) red[wid] = s;
    __syncthreads();
    float bs = 0.f;
    #pragma unroll
    for (int i = 0; i < 8; i++) bs += red[i];
    const float inv = 1.0f / bs;

    o2[2*tid]       = __floats2half2_rn(v[0]*inv, v[1]*inv);
    o2[2*tid+1]     = __floats2half2_rn(v[2]*inv, v[3]*inv);
    o2[512 + 2*tid] = __floats2half2_rn(v[4]*inv, v[5]*inv);
    o2[513 + 2*tid] = __floats2half2_rn(v[6]*inv, v[7]*inv);
}

// ---------------------------------------------------------------------------
// Launch
// ---------------------------------------------------------------------------
#define SMEM_256 ((AS_H + 256*SSTH) * 2 * 4)   // 122880 B
#define SMEM_128 ((AS_H + 128*SSTH) * 2 * 4)   // 81920 B

extern "C" void kernel_launch(void* const* d_in, const int* in_sizes, int n_in,
                              void* d_out, int out_size)
{
    const float* x    = (const float*)d_in[0];   // [4,2048,256]
    const float* Wqkv = (const float*)d_in[1];   // [256,6144]
    const float* Wout = (const float*)d_in[2];   // [2048,256]
    float* out = (float*)d_out;                  // [4,2048,256]

    cudaFuncSetAttribute((const void*)tgemm<0,256>, cudaFuncAttributeMaxDynamicSharedMemorySize, SMEM_256);
    cudaFuncSetAttribute((const void*)tgemm<1,256>, cudaFuncAttributeMaxDynamicSharedMemorySize, SMEM_256);
    cudaFuncSetAttribute((const void*)tgemm<2,256>, cudaFuncAttributeMaxDynamicSharedMemorySize, SMEM_256);
    cudaFuncSetAttribute((const void*)tgemm<3,128>, cudaFuncAttributeMaxDynamicSharedMemorySize, SMEM_128);

    conv_x_k<<<(BQ*LQ*EQ)/1024, 256>>>(x);
    transpose_k<0><<<dim3((3*HQ*EQ)/32, EQ/32), 256>>>(Wqkv);
    transpose_k<1><<<dim3(EQ/32, (HQ*EQ)/32), 256>>>(Wout);

    // 1) QKV projection + scatter
    tgemm<0,256><<<dim3((3*HQ*EQ)/256, (BQ*LQ)/BMT, 1), 256, SMEM_256>>>(nullptr, 0);

    // 2-4) per-group attention: scores -> softmax -> PV
    for (int g = 0; g < (BQ*HQ)/GRP; g++) {
        const int zoff = g * GRP;
        tgemm<1,256><<<dim3(LQ/256, LQ/BMT, GRP), 256, SMEM_256>>>(nullptr, zoff);
        softmax_k<<<GRP*LQ, 256>>>();
        tgemm<2,256><<<dim3(EQ/256, LQ/BMT, GRP), 256, SMEM_256>>>(nullptr, zoff);
    }

    // 5) out = att @ W_out
    tgemm<3,128><<<dim3(EQ/128, (BQ*LQ)/BMT, 1), 256, SMEM_128>>>(out, 0);
}

// round 9
// speedup vs baseline: 6.7306x; 1.3039x over previous
#include <cuda_runtime.h>
#include <cuda_fp16.h>
#include <cstdint>
#include <math.h>

#define BQ 4
#define LQ 2048
#define EQ 256
#define HQ 8
#define DH 256     // head dim

// ---------------------------------------------------------------------------
// Scratch (allocation-free device globals, ~132 MB)
// ---------------------------------------------------------------------------
__device__ __half g_xh   [BQ*LQ*EQ];              // x in fp16
__device__ __half g_qh   [BQ*HQ*LQ*DH];           // [bh][l][e], pre-scaled 1/16*log2e
__device__ __half g_kh   [BQ*HQ*LQ*DH];           // [bh][l][e]
__device__ __half g_vh   [BQ*HQ*LQ*DH];           // [bh][l][e] (natural)
__device__ __half g_atth [(size_t)BQ*LQ*HQ*EQ];   // [b][l][h*E+e]
__device__ __half g_wqkvTh[3*HQ*EQ*EQ];           // [6144][256]
__device__ __half g_woutTh[EQ*HQ*EQ];             // [256][2048]

static __device__ __forceinline__ uint32_t smem_u32(const void* p) {
    uint32_t a;
    asm("{ .reg .u64 t; cvta.to.shared.u64 t, %1; cvt.u32.u64 %0, t; }" : "=r"(a) : "l"(p));
    return a;
}
static __device__ __forceinline__ float ex2f(float x) {
    float r; asm("ex2.approx.f32 %0, %1;" : "=f"(r) : "f"(x)); return r;
}
// pack two fp32 -> one b32 reg of f16x2 (lo = a, hi = b)
static __device__ __forceinline__ uint32_t pack_half2(float a, float b) {
    uint32_t u;
    asm("cvt.rn.f16x2.f32 %0, %1, %2;" : "=r"(u) : "f"(b), "f"(a));
    return u;
}
#define CP_ASYNC16(d, s) \
    asm volatile("cp.async.cg.shared.global [%0], [%1], 16;" :: "r"(d), "l"(s))
#define CP_COMMIT() asm volatile("cp.async.commit_group;" ::: "memory")
template<int N> static __device__ __forceinline__ void cp_wait() {
    asm volatile("cp.async.wait_group %0;" :: "n"(N) : "memory");
}
#define LDSM4(r0, r1, r2, r3, a)                                              \
    asm volatile("ldmatrix.sync.aligned.m8n8.x4.shared.b16 {%0,%1,%2,%3}, [%4];" \
        : "=r"(r0), "=r"(r1), "=r"(r2), "=r"(r3) : "r"(a))
#define LDSM4T(r0, r1, r2, r3, a)                                             \
    asm volatile("ldmatrix.sync.aligned.m8n8.x4.trans.shared.b16 {%0,%1,%2,%3}, [%4];" \
        : "=r"(r0), "=r"(r1), "=r"(r2), "=r"(r3) : "r"(a))
#define MMA_F16(c, a0, a1, a2, a3, b0, b1)                                    \
    asm volatile("mma.sync.aligned.m16n8k16.row.col.f32.f16.f16.f32 "         \
        "{%0,%1,%2,%3}, {%4,%5,%6,%7}, {%8,%9}, {%0,%1,%2,%3};"               \
        : "+f"((c)[0]), "+f"((c)[1]), "+f"((c)[2]), "+f"((c)[3])              \
        : "r"(a0), "r"(a1), "r"(a2), "r"(a3), "r"(b0), "r"(b1))

// ---------------------------------------------------------------------------
// Flash attention: one CTA = (bh, 128 q rows). 256 thr, 8 warps x 16 rows.
// Q resident in smem; K/V streamed in 64-row double-buffered tiles.
// S/P in register fragments; online softmax (base-2, log2e folded into Q).
// ---------------------------------------------------------------------------
#define RQ 128         // q rows per CTA
#define TKV 64         // kv rows per tile
#define SST 264        // smem row stride (halves)
#define QH (RQ*SST)    // Q halves
#define KVH (TKV*SST)  // K or V tile halves
#define FLASH_SMEM ((QH + 4*KVH) * 2)   // 202752 B

__global__ void __launch_bounds__(256)
flash_k()
{
    extern __shared__ __align__(16) __half sm[];
    const int bh = blockIdx.y;
    const int qb = blockIdx.x;
    const __half* Qg = g_qh + (size_t)bh*LQ*DH + (size_t)qb*RQ*DH;
    const __half* Kg = g_kh + (size_t)bh*LQ*DH;
    const __half* Vg = g_vh + (size_t)bh*LQ*DH;

    const int tid = threadIdx.x;
    const uint32_t sbase = smem_u32(sm);

    // ---- load Q (async) ----
    #pragma unroll
    for (int j = 0; j < 16; j++) {
        const int idx = tid + 256*j;
        const int row = idx >> 5, ch = idx & 31;
        CP_ASYNC16(sbase + 2*(uint32_t)(row*SST + ch*8), Qg + (size_t)row*DH + ch*8);
    }
    CP_COMMIT();

    auto issueKV = [&](int t, int st) {
        const int kv0 = t * TKV;
        const uint32_t kb = sbase + 2*(uint32_t)(QH + st*2*KVH);
        #pragma unroll
        for (int j = 0; j < 8; j++) {
            const int idx = tid + 256*j;
            const int row = idx >> 5, ch = idx & 31;
            CP_ASYNC16(kb + 2*(uint32_t)(row*SST + ch*8),
                       Kg + (size_t)(kv0 + row)*DH + ch*8);
            CP_ASYNC16(kb + 2*(uint32_t)(KVH + row*SST + ch*8),
                       Vg + (size_t)(kv0 + row)*DH + ch*8);
        }
    };
    issueKV(0, 0);
    CP_COMMIT();

    const int wid = tid >> 5, lane = tid & 31;
    const int grp = lane >> 2, tig = lane & 3;

    const uint32_t aoff = (uint32_t)((wid*16 + (lane & 15)) * SST + (lane >> 4) * 8);
    const uint32_t boff = (uint32_t)(((lane & 7) + ((lane & 16) >> 1)) * SST + (lane & 8));

    float o[32][4];
    #pragma unroll
    for (int j = 0; j < 32; j++)
        #pragma unroll
        for (int i = 0; i < 4; i++) o[j][i] = 0.f;
    float m0 = -1e30f, m1 = -1e30f, l0 = 0.f, l1 = 0.f;

    const int NT = LQ / TKV;   // 32
    for (int t = 0; t < NT; t++) {
        if (t + 1 < NT) { issueKV(t + 1, (t + 1) & 1); CP_COMMIT(); cp_wait<1>(); }
        else            { cp_wait<0>(); }
        __syncthreads();

        const uint32_t kb = sbase + 2*(uint32_t)(QH + (t & 1)*2*KVH) + 2*boff;
        const uint32_t vb = kb + 2*(uint32_t)KVH;

        // ---- S = Q @ K^T (16 x 64 per warp) ----
        float s[8][4];
        #pragma unroll
        for (int j = 0; j < 8; j++)
            #pragma unroll
            for (int i = 0; i < 4; i++) s[j][i] = 0.f;

        #pragma unroll
        for (int ks = 0; ks < 16; ks++) {
            uint32_t a0, a1, a2, a3;
            LDSM4(a0, a1, a2, a3, sbase + 2*(aoff + (uint32_t)(ks*16)));
            #pragma unroll
            for (int ng = 0; ng < 4; ng++) {
                uint32_t b0, b1, b2, b3;
                LDSM4(b0, b1, b2, b3, kb + 2*(uint32_t)(ng*16*SST + ks*16));
                MMA_F16(s[2*ng],     a0, a1, a2, a3, b0, b1);
                MMA_F16(s[2*ng + 1], a0, a1, a2, a3, b2, b3);
            }
        }

        // ---- online softmax (rows grp / grp+8) ----
        float mr0 = s[0][0], mr1 = s[0][2];
        #pragma unroll
        for (int j = 0; j < 8; j++) {
            mr0 = fmaxf(mr0, fmaxf(s[j][0], s[j][1]));
            mr1 = fmaxf(mr1, fmaxf(s[j][2], s[j][3]));
        }
        mr0 = fmaxf(mr0, __shfl_xor_sync(0xffffffffu, mr0, 1));
        mr0 = fmaxf(mr0, __shfl_xor_sync(0xffffffffu, mr0, 2));
        mr1 = fmaxf(mr1, __shfl_xor_sync(0xffffffffu, mr1, 1));
        mr1 = fmaxf(mr1, __shfl_xor_sync(0xffffffffu, mr1, 2));

        const float mn0 = fmaxf(m0, mr0), mn1 = fmaxf(m1, mr1);
        const float sc0 = ex2f(m0 - mn0), sc1 = ex2f(m1 - mn1);
        m0 = mn0; m1 = mn1;

        float sum0 = 0.f, sum1 = 0.f;
        #pragma unroll
        for (int j = 0; j < 8; j++) {
            s[j][0] = ex2f(s[j][0] - m0);  sum0 += s[j][0];
            s[j][1] = ex2f(s[j][1] - m0);  sum0 += s[j][1];
            s[j][2] = ex2f(s[j][2] - m1);  sum1 += s[j][2];
            s[j][3] = ex2f(s[j][3] - m1);  sum1 += s[j][3];
        }
        sum0 += __shfl_xor_sync(0xffffffffu, sum0, 1);
        sum0 += __shfl_xor_sync(0xffffffffu, sum0, 2);
        sum1 += __shfl_xor_sync(0xffffffffu, sum1, 1);
        sum1 += __shfl_xor_sync(0xffffffffu, sum1, 2);
        l0 = l0 * sc0 + sum0;
        l1 = l1 * sc1 + sum1;

        #pragma unroll
        for (int j = 0; j < 32; j++) {
            o[j][0] *= sc0;  o[j][1] *= sc0;
            o[j][2] *= sc1;  o[j][3] *= sc1;
        }

        // ---- O += P @ V  (C-frag -> A-frag repack in registers) ----
        #pragma unroll
        for (int kt = 0; kt < 4; kt++) {
            const uint32_t a0 = pack_half2(s[2*kt][0],     s[2*kt][1]);
            const uint32_t a1 = pack_half2(s[2*kt][2],     s[2*kt][3]);
            const uint32_t a2 = pack_half2(s[2*kt + 1][0], s[2*kt + 1][1]);
            const uint32_t a3 = pack_half2(s[2*kt + 1][2], s[2*kt + 1][3]);
            #pragma unroll
            for (int eg = 0; eg < 16; eg++) {
                uint32_t v0, v1, v2, v3;
                LDSM4T(v0, v1, v2, v3, vb + 2*(uint32_t)(kt*16*SST + eg*16));
                MMA_F16(o[2*eg],     a0, a1, a2, a3, v0, v2);
                MMA_F16(o[2*eg + 1], a0, a1, a2, a3, v1, v3);
            }
        }
        __syncthreads();
    }

    // ---- epilogue: O /= l, write fp16 concat layout ----
    const float rl0 = 1.f / l0, rl1 = 1.f / l1;
    const int b = bh >> 3, h = bh & 7;
    const int tok0 = qb*RQ + wid*16 + grp;
    uint32_t* base0 = reinterpret_cast<uint32_t*>(
        g_atth + ((size_t)(b*LQ + tok0))*(HQ*EQ) + h*DH);
    uint32_t* base1 = reinterpret_cast<uint32_t*>(
        g_atth + ((size_t)(b*LQ + tok0 + 8))*(HQ*EQ) + h*DH);
    #pragma unroll
    for (int j = 0; j < 32; j++) {
        const int c2 = (j*8 + tig*2) >> 1;   // half2 index within head slice
        base0[c2] = pack_half2(o[j][0]*rl0, o[j][1]*rl0);
        base1[c2] = pack_half2(o[j][2]*rl1, o[j][3]*rl1);
    }
}

// ---------------------------------------------------------------------------
// fp16 mma GEMM (R7 core): C[M,N] = A[M,K] @ B[N,K]^T
// MODE 0 (BNTT=256): qkv = xh @ WqkvTh^T  scatter q*scale / k / v
// MODE 3 (BNTT=128): out = att @ WoutTh^T -> fp32
// ---------------------------------------------------------------------------
#define BMT 128
#define BKT 32
#define SSTH 40
#define AS_H (128*SSTH)

template<int MODE, int BNTT>
__global__ void __launch_bounds__(256)
tgemm(float* __restrict__ OUT)
{
    constexpr int NT2   = BNTT / 64;
    constexpr int BS_H  = BNTT * SSTH;
    constexpr int STG_B = (AS_H + BS_H) * 2;

    extern __shared__ __align__(16) __half smh[];

    const __half* A; const __half* B; int lda, ldb, K;
    if (MODE == 0) { A = g_xh;   lda = EQ;    B = g_wqkvTh; ldb = EQ;    K = EQ; }
    else           { A = g_atth; lda = HQ*EQ; B = g_woutTh; ldb = HQ*EQ; K = HQ*EQ; }

    const int tid  = threadIdx.x;
    const int rowBase = blockIdx.y * BMT;
    const int colBase = blockIdx.x * BNTT;

    const int lrow  = tid >> 2;
    const int lslot = tid & 3;
    const __half* Ag = A + (size_t)(rowBase + lrow) * lda + lslot * 8;
    const __half* Bg = B + (size_t)(colBase + lrow) * ldb + lslot * 8;
    const uint32_t sbase = smem_u32(smh);
    const uint32_t soff  = (uint32_t)(lrow * SSTH + lslot * 8) * 2;

    const int wid  = tid >> 5, lane = tid & 31;
    const int grp  = lane >> 2, tig = lane & 3;
    const int wm   = (wid >> 2) * 64;
    const int wn   = (wid & 3) * (BNTT / 4);

    const uint32_t aoffh = (uint32_t)((wm + (lane & 15)) * SSTH + ((lane >> 4) * 8));
    const uint32_t boffh = (uint32_t)((wn + (lane & 7) + ((lane & 16) >> 1)) * SSTH + (lane & 8));

    float c[4][NT2][2][4];
    #pragma unroll
    for (int mt = 0; mt < 4; mt++)
        #pragma unroll
        for (int n2 = 0; n2 < NT2; n2++)
            #pragma unroll
            for (int s = 0; s < 2; s++)
                #pragma unroll
                for (int i = 0; i < 4; i++) c[mt][n2][s][i] = 0.f;

    const int nk = K / BKT;

    auto issue = [&](int kt, int st) {
        const int k0 = kt * BKT;
        const uint32_t dA = sbase + st * STG_B + soff;
        CP_ASYNC16(dA,             Ag + k0);
        CP_ASYNC16(dA + 2*64*SSTH, Ag + k0 + (size_t)64 * lda);
        const uint32_t dB = sbase + st * STG_B + 2*AS_H + soff;
        #pragma unroll
        for (int i = 0; i < BNTT/64; i++)
            CP_ASYNC16(dB + i*2*64*SSTH, Bg + k0 + (size_t)(64*i) * ldb);
    };
    auto compute = [&](int st) {
        const uint32_t ab = sbase + st * STG_B + 2*aoffh;
        const uint32_t bb = sbase + st * STG_B + 2*AS_H + 2*boffh;
        #pragma unroll
        for (int ks = 0; ks < 2; ks++) {
            uint32_t af[4][4];
            #pragma unroll
            for (int mt = 0; mt < 4; mt++)
                LDSM4(af[mt][0], af[mt][1], af[mt][2], af[mt][3],
                      ab + 2*(uint32_t)(mt*16*SSTH + ks*16));
            #pragma unroll
            for (int n2 = 0; n2 < NT2; n2++) {
                uint32_t b0, b1, b2, b3;
                LDSM4(b0, b1, b2, b3, bb + 2*(uint32_t)(n2*16*SSTH + ks*16));
                #pragma unroll
                for (int mt = 0; mt < 4; mt++) {
                    MMA_F16(c[mt][n2][0], af[mt][0], af[mt][1], af[mt][2], af[mt][3], b0, b1);
                    MMA_F16(c[mt][n2][1], af[mt][0], af[mt][1], af[mt][2], af[mt][3], b2, b3);
                }
            }
        }
    };

    #pragma unroll
    for (int s = 0; s < 3; s++) { issue(s, s); CP_COMMIT(); }
    for (int kt = 0; kt < nk; kt++) {
        cp_wait<2>();
        __syncthreads();
        if (kt + 3 < nk) issue(kt + 3, (kt + 3) & 3);
        CP_COMMIT();
        compute(kt & 3);
    }

    #pragma unroll
    for (int mt = 0; mt < 4; mt++) {
        #pragma unroll
        for (int n2 = 0; n2 < NT2; n2++) {
            #pragma unroll
            for (int s = 0; s < 2; s++) {
                const int row0 = rowBase + wm + mt*16 + grp;
                const int cloc = wn + (n2*2 + s)*8 + tig*2;
                const float* cc = c[mt][n2][s];

                if (MODE == 0) {
                    const int part = colBase >> 11;
                    const int h    = (colBase >> 8) & 7;
                    const int e    = cloc;
                    const float qs = 0.0625f * 1.44269504f;   // 1/sqrt(256)*log2(e)
                    #pragma unroll
                    for (int hh = 0; hh < 2; hh++) {
                        const int m = row0 + hh*8;
                        const int b = m >> 11, ltok = m & (LQ-1);
                        const size_t bh = (size_t)(b*HQ + h);
                        const float v0 = cc[hh*2], v1 = cc[hh*2+1];
                        if (part == 0) {
                            *reinterpret_cast<uint32_t*>(g_qh + (bh*LQ + ltok)*DH + e) =
                                pack_half2(v0 * qs, v1 * qs);
                        } else if (part == 1) {
                            *reinterpret_cast<uint32_t*>(g_kh + (bh*LQ + ltok)*DH + e) =
                                pack_half2(v0, v1);
                        } else {
                            *reinterpret_cast<uint32_t*>(g_vh + (bh*LQ + ltok)*DH + e) =
                                pack_half2(v0, v1);
                        }
                    }
                } else {
                    const int col = colBase + cloc;
                    *reinterpret_cast<float2*>(OUT + (size_t)row0*EQ + col)     = make_float2(cc[0], cc[1]);
                    *reinterpret_cast<float2*>(OUT + (size_t)(row0+8)*EQ + col) = make_float2(cc[2], cc[3]);
                }
            }
        }
    }
}

// ---------------------------------------------------------------------------
// x -> fp16 (elementwise, vectorized)
// ---------------------------------------------------------------------------
__global__ void __launch_bounds__(256) conv_x_k(const float* __restrict__ x)
{
    const int i = blockIdx.x * 256 + threadIdx.x;
    float4 v = reinterpret_cast<const float4*>(x)[i];
    uint32_t* o = reinterpret_cast<uint32_t*>(g_xh);
    o[2*i]   = pack_half2(v.x, v.y);
    o[2*i+1] = pack_half2(v.z, v.w);
}

// ---------------------------------------------------------------------------
// Weight transpose + fp16 convert (tiny)
// ---------------------------------------------------------------------------
template<int WM>
__global__ void __launch_bounds__(256) transpose_k(const float* __restrict__ src)
{
    constexpr int R = (WM == 0) ? EQ : HQ*EQ;
    constexpr int C = (WM == 0) ? 3*HQ*EQ : EQ;
    __half* dst = (WM == 0) ? g_wqkvTh : g_woutTh;
    __shared__ float t[32][33];
    const int c0 = blockIdx.x * 32, r0 = blockIdx.y * 32;
    const int tx = threadIdx.x & 31, ty = threadIdx.x >> 5;
    #pragma unroll
    for (int i = 0; i < 4; i++)
        t[ty + i*8][tx] = src[(size_t)(r0 + ty + i*8) * C + c0 + tx];
    __syncthreads();
    #pragma unroll
    for (int i = 0; i < 4; i++)
        dst[(size_t)(c0 + ty + i*8) * R + r0 + tx] = __float2half_rn(t[tx][ty + i*8]);
}

// ---------------------------------------------------------------------------
// Launch
// ---------------------------------------------------------------------------
#define SMEM_256 ((AS_H + 256*SSTH) * 2 * 4)   // 122880 B
#define SMEM_128 ((AS_H + 128*SSTH) * 2 * 4)   // 81920 B

extern "C" void kernel_launch(void* const* d_in, const int* in_sizes, int n_in,
                              void* d_out, int out_size)
{
    const float* x    = (const float*)d_in[0];   // [4,2048,256]
    const float* Wqkv = (const float*)d_in[1];   // [256,6144]
    const float* Wout = (const float*)d_in[2];   // [2048,256]
    float* out = (float*)d_out;                  // [4,2048,256]

    cudaFuncSetAttribute((const void*)tgemm<0,256>, cudaFuncAttributeMaxDynamicSharedMemorySize, SMEM_256);
    cudaFuncSetAttribute((const void*)tgemm<3,128>, cudaFuncAttributeMaxDynamicSharedMemorySize, SMEM_128);
    cudaFuncSetAttribute((const void*)flash_k,      cudaFuncAttributeMaxDynamicSharedMemorySize, FLASH_SMEM);

    conv_x_k<<<(BQ*LQ*EQ)/1024, 256>>>(x);
    transpose_k<0><<<dim3((3*HQ*EQ)/32, EQ/32), 256>>>(Wqkv);
    transpose_k<1><<<dim3(EQ/32, (HQ*EQ)/32), 256>>>(Wout);

    // 1) QKV projection + scatter (q scaled by 1/16*log2e, k, v natural)
    tgemm<0,256><<<dim3((3*HQ*EQ)/256, (BQ*LQ)/BMT, 1), 256, SMEM_256>>>(nullptr);

    // 2) fused flash attention -> g_atth
    flash_k<<<dim3(LQ/RQ, BQ*HQ), 256, FLASH_SMEM>>>();

    // 3) out = att @ W_out
    tgemm<3,128><<<dim3(EQ/128, (BQ*LQ)/BMT, 1), 256, SMEM_128>>>(out);
}